// round 1
// baseline (speedup 1.0000x reference)
#include <cuda_runtime.h>

// QuantumOperator: out = (sr + i*si) @ (Or + i*Oi) where
//   Or = p p^T with diag replaced by sigmoid(p)  -> p p^T + diag(sigmoid(p) - p^2)
//   Oi = p 1^T - 1 p^T   (antisymmetric, zero diag)
//
// Per-row closed form (a_r = sr.p, a_i = si.p, s_r = sum sr, s_i = sum si,
// d_j = sigmoid(p_j) - p_j^2):
//   out_real[j] = (a_r + s_i) * p_j + d_j * sr[j] - a_i
//   out_imag[j] = (a_i - s_r) * p_j + d_j * si[j] + a_r
//
// Pure streaming kernel: ~537 MB traffic total, memory-bound.

#define DIM 128

__global__ __launch_bounds__(256) void quantum_op_kernel(
    const float* __restrict__ sr,
    const float* __restrict__ si,
    const float* __restrict__ p,
    float* __restrict__ out_real,
    float* __restrict__ out_imag,
    int M)
{
    const int lane = threadIdx.x & 31;
    const int warp_global = (blockIdx.x * blockDim.x + threadIdx.x) >> 5;
    const int nwarps = (gridDim.x * blockDim.x) >> 5;

    // Each lane owns 4 consecutive columns: [4*lane, 4*lane+4)
    const float4 p4 = reinterpret_cast<const float4*>(p)[lane];
    float4 d4;
    d4.x = 1.0f / (1.0f + __expf(-p4.x)) - p4.x * p4.x;
    d4.y = 1.0f / (1.0f + __expf(-p4.y)) - p4.y * p4.y;
    d4.z = 1.0f / (1.0f + __expf(-p4.z)) - p4.z * p4.z;
    d4.w = 1.0f / (1.0f + __expf(-p4.w)) - p4.w * p4.w;

    for (int row = warp_global; row < M; row += nwarps) {
        const float4 a = reinterpret_cast<const float4*>(sr + (size_t)row * DIM)[lane];
        const float4 b = reinterpret_cast<const float4*>(si + (size_t)row * DIM)[lane];

        float ar = a.x * p4.x + a.y * p4.y + a.z * p4.z + a.w * p4.w; // sr . p
        float ai = b.x * p4.x + b.y * p4.y + b.z * p4.z + b.w * p4.w; // si . p
        float srs = a.x + a.y + a.z + a.w;                            // sum sr
        float sis = b.x + b.y + b.z + b.w;                            // sum si

        #pragma unroll
        for (int off = 16; off > 0; off >>= 1) {
            ar  += __shfl_xor_sync(0xFFFFFFFFu, ar,  off);
            ai  += __shfl_xor_sync(0xFFFFFFFFu, ai,  off);
            srs += __shfl_xor_sync(0xFFFFFFFFu, srs, off);
            sis += __shfl_xor_sync(0xFFFFFFFFu, sis, off);
        }

        const float cr = ar + sis;  // coefficient of p_j in out_real
        const float ci = ai - srs;  // coefficient of p_j in out_imag

        float4 orr, oii;
        orr.x = cr * p4.x + d4.x * a.x - ai;
        orr.y = cr * p4.y + d4.y * a.y - ai;
        orr.z = cr * p4.z + d4.z * a.z - ai;
        orr.w = cr * p4.w + d4.w * a.w - ai;

        oii.x = ci * p4.x + d4.x * b.x + ar;
        oii.y = ci * p4.y + d4.y * b.y + ar;
        oii.z = ci * p4.z + d4.z * b.z + ar;
        oii.w = ci * p4.w + d4.w * b.w + ar;

        reinterpret_cast<float4*>(out_real + (size_t)row * DIM)[lane] = orr;
        reinterpret_cast<float4*>(out_imag + (size_t)row * DIM)[lane] = oii;
    }
}

extern "C" void kernel_launch(void* const* d_in, const int* in_sizes, int n_in,
                              void* d_out, int out_size) {
    const float* sr = (const float*)d_in[0];
    const float* si = (const float*)d_in[1];
    const float* p  = (const float*)d_in[2];
    float* out = (float*)d_out;

    const int M = in_sizes[0] / DIM;            // 16*16384 = 262144 rows
    float* out_real = out;                       // first half
    float* out_imag = out + (size_t)M * DIM;     // second half

    const int threads = 256;
    const int blocks = 2048;  // grid-stride; ~16 rows per warp
    quantum_op_kernel<<<blocks, threads>>>(sr, si, p, out_real, out_imag, M);
}

// round 2
// speedup vs baseline: 1.0018x; 1.0018x over previous
#include <cuda_runtime.h>

// QuantumOperator closed form (see R1):
//   out_real[j] = (sr.p + sum(si)) * p_j + d_j * sr[j] - si.p
//   out_imag[j] = (si.p - sum(sr)) * p_j + d_j * si[j] + sr.p
//   d_j = sigmoid(p_j) - p_j^2
//
// Streaming, HBM-bound. This revision software-pipelines: prefetch the next
// 2-row chunk's 4x LDG.128 before the current chunk's shuffle reduction, so
// loads stay in flight across the whole compute phase (Little's law fill).

#define DIM 128

__device__ __forceinline__ float dot4(const float4 a, const float4 b) {
    return a.x * b.x + a.y * b.y + a.z * b.z + a.w * b.w;
}
__device__ __forceinline__ float hsum4(const float4 a) {
    return a.x + a.y + a.z + a.w;
}

__global__ void __launch_bounds__(256) quantum_op_kernel(
    const float4* __restrict__ srv,
    const float4* __restrict__ siv,
    const float* __restrict__ p,
    float4* __restrict__ out_real,
    float4* __restrict__ out_imag,
    int M)
{
    const int lane = threadIdx.x & 31;
    const int warp = blockIdx.x * (blockDim.x >> 5) + (threadIdx.x >> 5);
    const int nwarps = gridDim.x * (blockDim.x >> 5);

    const float4 p4 = reinterpret_cast<const float4*>(p)[lane];
    float4 d4;
    d4.x = 1.0f / (1.0f + __expf(-p4.x)) - p4.x * p4.x;
    d4.y = 1.0f / (1.0f + __expf(-p4.y)) - p4.y * p4.y;
    d4.z = 1.0f / (1.0f + __expf(-p4.z)) - p4.z * p4.z;
    d4.w = 1.0f / (1.0f + __expf(-p4.w)) - p4.w * p4.w;

    int row = warp * 2;              // M is a multiple of 2
    const int stride = nwarps * 2;
    if (row >= M) return;

    // Initial chunk load (rows row, row+1 of both arrays)
    float4 a0 = __ldcs(&srv[(size_t)row * 32 + lane]);
    float4 a1 = __ldcs(&srv[(size_t)(row + 1) * 32 + lane]);
    float4 b0 = __ldcs(&siv[(size_t)row * 32 + lane]);
    float4 b1 = __ldcs(&siv[(size_t)(row + 1) * 32 + lane]);

    while (true) {
        const int nrow = row + stride;
        const bool has_next = nrow < M;

        // ---- Prefetch next chunk BEFORE the reduction (keeps 4 LDG in flight
        //      during the entire shuffle/compute/store phase) ----
        float4 na0, na1, nb0, nb1;
        if (has_next) {
            na0 = __ldcs(&srv[(size_t)nrow * 32 + lane]);
            na1 = __ldcs(&srv[(size_t)(nrow + 1) * 32 + lane]);
            nb0 = __ldcs(&siv[(size_t)nrow * 32 + lane]);
            nb1 = __ldcs(&siv[(size_t)(nrow + 1) * 32 + lane]);
        }

        // ---- Per-row reductions: 8 independent butterfly chains ----
        float ar0 = dot4(a0, p4), ai0 = dot4(b0, p4);
        float sr0 = hsum4(a0),    si0 = hsum4(b0);
        float ar1 = dot4(a1, p4), ai1 = dot4(b1, p4);
        float sr1 = hsum4(a1),    si1 = hsum4(b1);

        #pragma unroll
        for (int off = 16; off > 0; off >>= 1) {
            ar0 += __shfl_xor_sync(0xFFFFFFFFu, ar0, off);
            ai0 += __shfl_xor_sync(0xFFFFFFFFu, ai0, off);
            sr0 += __shfl_xor_sync(0xFFFFFFFFu, sr0, off);
            si0 += __shfl_xor_sync(0xFFFFFFFFu, si0, off);
            ar1 += __shfl_xor_sync(0xFFFFFFFFu, ar1, off);
            ai1 += __shfl_xor_sync(0xFFFFFFFFu, ai1, off);
            sr1 += __shfl_xor_sync(0xFFFFFFFFu, sr1, off);
            si1 += __shfl_xor_sync(0xFFFFFFFFu, si1, off);
        }

        // ---- Compute + store row 0 ----
        {
            const float cr = ar0 + si0, ci = ai0 - sr0;
            float4 orr, oii;
            orr.x = cr * p4.x + d4.x * a0.x - ai0;
            orr.y = cr * p4.y + d4.y * a0.y - ai0;
            orr.z = cr * p4.z + d4.z * a0.z - ai0;
            orr.w = cr * p4.w + d4.w * a0.w - ai0;
            oii.x = ci * p4.x + d4.x * b0.x + ar0;
            oii.y = ci * p4.y + d4.y * b0.y + ar0;
            oii.z = ci * p4.z + d4.z * b0.z + ar0;
            oii.w = ci * p4.w + d4.w * b0.w + ar0;
            __stcs(&out_real[(size_t)row * 32 + lane], orr);
            __stcs(&out_imag[(size_t)row * 32 + lane], oii);
        }
        // ---- Compute + store row 1 ----
        {
            const float cr = ar1 + si1, ci = ai1 - sr1;
            float4 orr, oii;
            orr.x = cr * p4.x + d4.x * a1.x - ai1;
            orr.y = cr * p4.y + d4.y * a1.y - ai1;
            orr.z = cr * p4.z + d4.z * a1.z - ai1;
            orr.w = cr * p4.w + d4.w * a1.w - ai1;
            oii.x = ci * p4.x + d4.x * b1.x + ar1;
            oii.y = ci * p4.y + d4.y * b1.y + ar1;
            oii.z = ci * p4.z + d4.z * b1.z + ar1;
            oii.w = ci * p4.w + d4.w * b1.w + ar1;
            __stcs(&out_real[(size_t)(row + 1) * 32 + lane], orr);
            __stcs(&out_imag[(size_t)(row + 1) * 32 + lane], oii);
        }

        if (!has_next) break;
        row = nrow;
        a0 = na0; a1 = na1; b0 = nb0; b1 = nb1;
    }
}

extern "C" void kernel_launch(void* const* d_in, const int* in_sizes, int n_in,
                              void* d_out, int out_size) {
    const float* sr = (const float*)d_in[0];
    const float* si = (const float*)d_in[1];
    const float* p  = (const float*)d_in[2];
    float* out = (float*)d_out;

    const int M = in_sizes[0] / DIM;                 // 262144 rows
    float4* out_real = (float4*)out;
    float4* out_imag = (float4*)(out + (size_t)M * DIM);

    const int threads = 256;
    const int blocks = 1216;                         // ~8 blocks/SM, grid-stride
    quantum_op_kernel<<<blocks, threads>>>(
        (const float4*)sr, (const float4*)si, p, out_real, out_imag, M);
}

// round 3
// speedup vs baseline: 1.0245x; 1.0227x over previous
#include <cuda_runtime.h>

// QuantumOperator closed form:
//   d_j = sigmoid(p_j) - p_j^2
//   out_real[j] = (sr.p + sum(si)) * p_j + d_j * sr[j] - si.p
//   out_imag[j] = (si.p - sum(sr)) * p_j + d_j * si[j] + sr.p
//
// R3: 2-row batch, all 4 LDG.128 issued back-to-back at loop top (max MLP
// without double-buffer register cost). __ldcg loads (no L1), __stcs stores.

#define DIM 128

__device__ __forceinline__ float dot4(const float4 a, const float4 b) {
    return a.x * b.x + a.y * b.y + a.z * b.z + a.w * b.w;
}
__device__ __forceinline__ float hsum4(const float4 a) {
    return a.x + a.y + a.z + a.w;
}

__global__ void __launch_bounds__(256) quantum_op_kernel(
    const float4* __restrict__ srv,
    const float4* __restrict__ siv,
    const float* __restrict__ p,
    float4* __restrict__ out_real,
    float4* __restrict__ out_imag,
    int M)
{
    const int lane = threadIdx.x & 31;
    const int warp = blockIdx.x * (blockDim.x >> 5) + (threadIdx.x >> 5);
    const int nwarps = gridDim.x * (blockDim.x >> 5);

    const float4 p4 = reinterpret_cast<const float4*>(p)[lane];
    float4 d4;
    d4.x = 1.0f / (1.0f + __expf(-p4.x)) - p4.x * p4.x;
    d4.y = 1.0f / (1.0f + __expf(-p4.y)) - p4.y * p4.y;
    d4.z = 1.0f / (1.0f + __expf(-p4.z)) - p4.z * p4.z;
    d4.w = 1.0f / (1.0f + __expf(-p4.w)) - p4.w * p4.w;

    const int stride = nwarps * 2;

    for (int row = warp * 2; row < M; row += stride) {
        // ---- 4x LDG.128 back-to-back: 1KB in flight per warp ----
        const float4 a0 = __ldcg(&srv[(size_t)row * 32 + lane]);
        const float4 a1 = __ldcg(&srv[(size_t)(row + 1) * 32 + lane]);
        const float4 b0 = __ldcg(&siv[(size_t)row * 32 + lane]);
        const float4 b1 = __ldcg(&siv[(size_t)(row + 1) * 32 + lane]);

        // ---- 8 independent butterfly chains ----
        float ar0 = dot4(a0, p4), ai0 = dot4(b0, p4);
        float sr0 = hsum4(a0),    si0 = hsum4(b0);
        float ar1 = dot4(a1, p4), ai1 = dot4(b1, p4);
        float sr1 = hsum4(a1),    si1 = hsum4(b1);

        #pragma unroll
        for (int off = 16; off > 0; off >>= 1) {
            ar0 += __shfl_xor_sync(0xFFFFFFFFu, ar0, off);
            ai0 += __shfl_xor_sync(0xFFFFFFFFu, ai0, off);
            sr0 += __shfl_xor_sync(0xFFFFFFFFu, sr0, off);
            si0 += __shfl_xor_sync(0xFFFFFFFFu, si0, off);
            ar1 += __shfl_xor_sync(0xFFFFFFFFu, ar1, off);
            ai1 += __shfl_xor_sync(0xFFFFFFFFu, ai1, off);
            sr1 += __shfl_xor_sync(0xFFFFFFFFu, sr1, off);
            si1 += __shfl_xor_sync(0xFFFFFFFFu, si1, off);
        }

        {
            const float cr = ar0 + si0, ci = ai0 - sr0;
            float4 orr, oii;
            orr.x = cr * p4.x + d4.x * a0.x - ai0;
            orr.y = cr * p4.y + d4.y * a0.y - ai0;
            orr.z = cr * p4.z + d4.z * a0.z - ai0;
            orr.w = cr * p4.w + d4.w * a0.w - ai0;
            oii.x = ci * p4.x + d4.x * b0.x + ar0;
            oii.y = ci * p4.y + d4.y * b0.y + ar0;
            oii.z = ci * p4.z + d4.z * b0.z + ar0;
            oii.w = ci * p4.w + d4.w * b0.w + ar0;
            __stcs(&out_real[(size_t)row * 32 + lane], orr);
            __stcs(&out_imag[(size_t)row * 32 + lane], oii);
        }
        {
            const float cr = ar1 + si1, ci = ai1 - sr1;
            float4 orr, oii;
            orr.x = cr * p4.x + d4.x * a1.x - ai1;
            orr.y = cr * p4.y + d4.y * a1.y - ai1;
            orr.z = cr * p4.z + d4.z * a1.z - ai1;
            orr.w = cr * p4.w + d4.w * a1.w - ai1;
            oii.x = ci * p4.x + d4.x * b1.x + ar1;
            oii.y = ci * p4.y + d4.y * b1.y + ar1;
            oii.z = ci * p4.z + d4.z * b1.z + ar1;
            oii.w = ci * p4.w + d4.w * b1.w + ar1;
            __stcs(&out_real[(size_t)(row + 1) * 32 + lane], orr);
            __stcs(&out_imag[(size_t)(row + 1) * 32 + lane], oii);
        }
    }
}

extern "C" void kernel_launch(void* const* d_in, const int* in_sizes, int n_in,
                              void* d_out, int out_size) {
    const float* sr = (const float*)d_in[0];
    const float* si = (const float*)d_in[1];
    const float* p  = (const float*)d_in[2];
    float* out = (float*)d_out;

    const int M = in_sizes[0] / DIM;                 // 262144 rows
    float4* out_real = (float4*)out;
    float4* out_imag = (float4*)(out + (size_t)M * DIM);

    const int threads = 256;
    const int blocks = 2048;                         // 16384 warps, 8 iters each
    quantum_op_kernel<<<blocks, threads>>>(
        (const float4*)sr, (const float4*)si, p, out_real, out_imag, M);
}